// round 1
// baseline (speedup 1.0000x reference)
#include <cuda_runtime.h>
#include <math.h>

#define N_TOKEN 16384
#define DMODEL  4096
#define NEXP    16
#define NW      32          // 16 gate rows (w1) + 16 noise rows (wn)
#define NSEL    4
#define TOK_PB  64          // tokens per block
#define KC      64          // K chunk
#define NTHREADS 256
#define XS      68          // padded row stride (floats) for x_s / w_s (16B aligned, bank-shift 4)
#define HS      33          // padded stride for hsum

__device__ float g_imp[NEXP];
__device__ float g_load[NEXP];

__global__ void zero_kernel() {
    if (threadIdx.x < NEXP) { g_imp[threadIdx.x] = 0.f; g_load[threadIdx.x] = 0.f; }
}

__global__ __launch_bounds__(NTHREADS)
void gate_kernel(const float* __restrict__ x,
                 const float* __restrict__ w1,
                 const float* __restrict__ w2,
                 const float* __restrict__ wn,
                 const float* __restrict__ noise,
                 float* __restrict__ out)
{
    __shared__ __align__(16) float x_s[TOK_PB * XS];
    __shared__ __align__(16) float w_s[NW * XS];
    __shared__ float hsum[TOK_PB * HS];
    __shared__ float w2_s[NEXP * NEXP];
    __shared__ float imp_s[NEXP];
    __shared__ float load_s[NEXP];

    const int tid  = threadIdx.x;
    const int tok0 = blockIdx.x * TOK_PB;
    const int eg = tid & 7;          // expert group: experts eg + 8*j, j=0..3
    const int tg = (tid >> 3) & 7;   // token group:  tokens  tg + 8*i, i=0..7
    const int ks = tid >> 6;         // K-slice 0..3 within each chunk

    if (tid < NEXP * NEXP) w2_s[tid] = w2[tid];
    if (tid < NEXP) { imp_s[tid] = 0.f; load_s[tid] = 0.f; }

    float acc[8][4];
#pragma unroll
    for (int i = 0; i < 8; i++)
#pragma unroll
        for (int j = 0; j < 4; j++) acc[i][j] = 0.f;

    const float4* xs4 = (const float4*)x_s;
    const float4* ws4 = (const float4*)w_s;

    for (int kc = 0; kc < DMODEL; kc += KC) {
        // stage x tile: 64 tokens x 64 k  (coalesced float4 loads)
#pragma unroll
        for (int r = 0; r < 4; r++) {
            int idx = r * NTHREADS + tid;      // 0..1023
            int t = idx >> 4, q = idx & 15;
            float4 v = *(const float4*)(x + (size_t)(tok0 + t) * DMODEL + kc + q * 4);
            *(float4*)(x_s + t * XS + q * 4) = v;
        }
        // stage weight tile: 32 rows x 64 k (w1 rows then wn rows)
#pragma unroll
        for (int r = 0; r < 2; r++) {
            int idx = r * NTHREADS + tid;      // 0..511
            int e = idx >> 4, q = idx & 15;
            const float* wr = (e < NEXP) ? (w1 + (size_t)e * DMODEL)
                                         : (wn + (size_t)(e - NEXP) * DMODEL);
            *(float4*)(w_s + e * XS + q * 4) = *(const float4*)(wr + kc + q * 4);
        }
        __syncthreads();

#pragma unroll
        for (int u = 0; u < 4; u++) {
            const int kb = ks * 4 + u;         // float4 index within padded row
            float4 wv[4];
#pragma unroll
            for (int j = 0; j < 4; j++) wv[j] = ws4[(eg + 8 * j) * (XS / 4) + kb];
#pragma unroll
            for (int i = 0; i < 8; i++) {
                float4 xv = xs4[(tg + 8 * i) * (XS / 4) + kb];
#pragma unroll
                for (int j = 0; j < 4; j++) {
                    acc[i][j] = fmaf(xv.x, wv[j].x, acc[i][j]);
                    acc[i][j] = fmaf(xv.y, wv[j].y, acc[i][j]);
                    acc[i][j] = fmaf(xv.z, wv[j].z, acc[i][j]);
                    acc[i][j] = fmaf(xv.w, wv[j].w, acc[i][j]);
                }
            }
        }
        __syncthreads();
    }

    // reduce the 4 K-slices into hsum[token][expert]
    for (int r = 0; r < 4; r++) {
        if (ks == r) {
#pragma unroll
            for (int i = 0; i < 8; i++)
#pragma unroll
                for (int j = 0; j < 4; j++) {
                    int t = tg + 8 * i, e = eg + 8 * j;
                    if (r == 0) hsum[t * HS + e] = acc[i][j];
                    else        hsum[t * HS + e] += acc[i][j];
                }
        }
        __syncthreads();
    }

    // ---- epilogue: one thread per token ----
    if (tid < TOK_PB) {
        const int t = tid;
        const int tok = tok0 + t;

        float g[NEXP], ctrl[NEXP], lg[NEXP], ln[NEXP], lo[NEXP];
#pragma unroll
        for (int e = 0; e < NEXP; e++) g[e] = tanhf(hsum[t * HS + e]);
#pragma unroll
        for (int e = 0; e < NEXP; e++) {
            float v = hsum[t * HS + NEXP + e];
            float sp = (v > 20.f) ? v : log1pf(expf(v));
            ctrl[e] = sp + 0.01f;   // NOISE_EPS
        }
#pragma unroll
        for (int f = 0; f < NEXP; f++) {
            float s = 0.f;
#pragma unroll
            for (int e = 0; e < NEXP; e++) s = fmaf(g[e], w2_s[f * NEXP + e], s);
            lg[f] = s;
        }
#pragma unroll
        for (int f = 0; f < NEXP; f++) {
            ln[f] = noise[(size_t)tok * NEXP + f] * ctrl[f];
            lo[f] = lg[f] + ln[f];
        }

        // top-5 (stable: ties keep smaller index, matching jax.lax.top_k)
        float tv[5]; int tix[5]; unsigned used = 0;
#pragma unroll
        for (int p = 0; p < 5; p++) {
            float best = -1e30f; int bi = 0;
#pragma unroll
            for (int f = 0; f < NEXP; f++) {
                bool ok = !((used >> f) & 1u) && (lo[f] > best);
                best = ok ? lo[f] : best;
                bi   = ok ? f     : bi;
            }
            used |= 1u << bi;
            tv[p] = best; tix[p] = bi;
        }

        // softmax over top-4
        float ex[NSEL], ssum = 0.f;
#pragma unroll
        for (int p = 0; p < NSEL; p++) { ex[p] = expf(tv[p] - tv[0]); ssum += ex[p]; }
        float inv = 1.f / ssum;
#pragma unroll
        for (int p = 0; p < NSEL; p++) {
            float sc = ex[p] * inv;
            out[(size_t)tok * NSEL + p] = (float)tix[p];                        // indices
            out[(size_t)N_TOKEN * NSEL + (size_t)tok * NSEL + p] = sc;          // scores
            atomicAdd(&imp_s[tix[p]], sc);
        }

        // load = sum over tokens of P(selected)
        const float thr_in  = tv[4];   // 5th largest logit
        const float thr_out = tv[3];   // 4th largest logit
#pragma unroll
        for (int f = 0; f < NEXP; f++) {
            float thr = (ln[f] > thr_in) ? thr_in : thr_out;
            float z = (lg[f] - thr) / ctrl[f];
            atomicAdd(&load_s[f], normcdff(z));
        }
    }
    __syncthreads();
    if (tid < NEXP) {
        atomicAdd(&g_imp[tid],  imp_s[tid]);
        atomicAdd(&g_load[tid], load_s[tid]);
    }
}

__global__ void loss_kernel(float* __restrict__ out)
{
    if (threadIdx.x == 0) {
        double si = 0, sqi = 0, sl = 0, sql = 0;
        for (int e = 0; e < NEXP; e++) {
            double v = (double)g_imp[e];  si += v; sqi += v * v;
            double w = (double)g_load[e]; sl += w; sql += w * w;
        }
        double mi = si / NEXP, ml = sl / NEXP;
        double vi = (sqi - si * si / NEXP) / (NEXP - 1);   // ddof=1
        double vl = (sql - sl * sl / NEXP) / (NEXP - 1);
        double cv = vi / (mi * mi + 1e-10) + vl / (ml * ml + 1e-10);
        out[(size_t)2 * N_TOKEN * NSEL] = (float)(0.01 * cv);  // LOSS_LAMBDA
    }
}

extern "C" void kernel_launch(void* const* d_in, const int* in_sizes, int n_in,
                              void* d_out, int out_size)
{
    const float* x     = (const float*)d_in[0];
    const float* w1    = (const float*)d_in[1];
    const float* w2    = (const float*)d_in[2];
    const float* wn    = (const float*)d_in[3];
    const float* noise = (const float*)d_in[4];
    float* out = (float*)d_out;

    zero_kernel<<<1, 32>>>();
    gate_kernel<<<N_TOKEN / TOK_PB, NTHREADS>>>(x, w1, w2, wn, noise, out);
    loss_kernel<<<1, 32>>>(out);
}

// round 2
// speedup vs baseline: 1.1169x; 1.1169x over previous
#include <cuda_runtime.h>
#include <math.h>

#define N_TOKEN 16384
#define DMODEL  4096
#define NEXP    16
#define NW      32          // 16 gate rows (w1) + 16 noise rows (wn)
#define NSEL    4
#define TOK_PB  64          // tokens per block
#define KC      64          // K chunk
#define NTHREADS 256
#define NBLOCKS (N_TOKEN / TOK_PB)
#define XS      68          // padded row stride in floats (16B aligned, bank-shift 4/row)
#define XS2     17          // row stride in 16B units
#define HS      33          // padded stride for hsum

// x_s buffers: 2 * 64 * 68 = 8704 floats; w_s: 2 * 32 * 68 = 4352 floats
#define XBUF_FL (TOK_PB * XS)
#define WBUF_FL (NW * XS)
#define DSMEM_BYTES ((2 * XBUF_FL + 2 * WBUF_FL) * 4)

__device__ float g_part[NBLOCKS * 32];   // per-block [imp(16) | load(16)]

#define FMA2(acc, a, b) \
    asm("fma.rn.f32x2 %0, %1, %2, %0;" : "+l"(acc) : "l"(a), "l"(b))

#define CP_ASYNC16(dst_s, src_g) \
    asm volatile("cp.async.cg.shared.global [%0], [%1], 16;" :: "r"(dst_s), "l"(src_g))
#define CP_COMMIT() asm volatile("cp.async.commit_group;")
#define CP_WAIT1()  asm volatile("cp.async.wait_group 1;")

__global__ __launch_bounds__(NTHREADS, 2)
void gate_kernel(const float* __restrict__ x,
                 const float* __restrict__ w1,
                 const float* __restrict__ w2,
                 const float* __restrict__ wn,
                 const float* __restrict__ noise,
                 float* __restrict__ out)
{
    extern __shared__ __align__(16) float dsm[];
    float* x_s = dsm;                       // 2 buffers
    float* w_s = dsm + 2 * XBUF_FL;         // 2 buffers
    float* hsum = dsm;                      // aliased over x_s after mainloop

    __shared__ float w2_s[NEXP * NEXP];
    __shared__ float imp_s[NEXP];
    __shared__ float load_s[NEXP];

    const int tid  = threadIdx.x;
    const int tok0 = blockIdx.x * TOK_PB;
    const int eg = tid & 7;          // expert group: experts eg + 8*j
    const int tg = (tid >> 3) & 7;   // token group:  tokens  tg + 8*i
    const int ks = tid >> 6;         // K-slice 0..3

    if (tid < NEXP * NEXP) w2_s[tid] = w2[tid];
    if (tid < NEXP) { imp_s[tid] = 0.f; load_s[tid] = 0.f; }

    // staging indices (constant per thread)
    const int xt = tid >> 4;          // base token row for x staging (pattern uses idx>>4)
    const int xq = tid & 15;

    unsigned long long acc[8][4];
#pragma unroll
    for (int i = 0; i < 8; i++)
#pragma unroll
        for (int j = 0; j < 4; j++) acc[i][j] = 0ull;

    // ---- stage chunk 0 ----
    {
        float* xb = x_s;
        float* wb = w_s;
#pragma unroll
        for (int r = 0; r < 4; r++) {
            int idx = r * NTHREADS + tid;
            int t = idx >> 4, q = idx & 15;
            unsigned dst = (unsigned)__cvta_generic_to_shared(xb + t * XS + q * 4);
            CP_ASYNC16(dst, x + (size_t)(tok0 + t) * DMODEL + q * 4);
        }
#pragma unroll
        for (int r = 0; r < 2; r++) {
            int idx = r * NTHREADS + tid;
            int e = idx >> 4, q = idx & 15;
            const float* wr = (e < NEXP) ? (w1 + (size_t)e * DMODEL)
                                         : (wn + (size_t)(e - NEXP) * DMODEL);
            unsigned dst = (unsigned)__cvta_generic_to_shared(wb + e * XS + q * 4);
            CP_ASYNC16(dst, wr + q * 4);
        }
        CP_COMMIT();
    }

    for (int c = 0; c < DMODEL / KC; c++) {
        // prefetch chunk c+1 into the other buffer
        if (c + 1 < DMODEL / KC) {
            const int kc = (c + 1) * KC;
            float* xb = x_s + ((c + 1) & 1) * XBUF_FL;
            float* wb = w_s + ((c + 1) & 1) * WBUF_FL;
#pragma unroll
            for (int r = 0; r < 4; r++) {
                int idx = r * NTHREADS + tid;
                int t = idx >> 4, q = idx & 15;
                unsigned dst = (unsigned)__cvta_generic_to_shared(xb + t * XS + q * 4);
                CP_ASYNC16(dst, x + (size_t)(tok0 + t) * DMODEL + kc + q * 4);
            }
#pragma unroll
            for (int r = 0; r < 2; r++) {
                int idx = r * NTHREADS + tid;
                int e = idx >> 4, q = idx & 15;
                const float* wr = (e < NEXP) ? (w1 + (size_t)e * DMODEL)
                                             : (wn + (size_t)(e - NEXP) * DMODEL);
                unsigned dst = (unsigned)__cvta_generic_to_shared(wb + e * XS + q * 4);
                CP_ASYNC16(dst, wr + kc + q * 4);
            }
        }
        CP_COMMIT();
        CP_WAIT1();          // current buffer's group complete
        __syncthreads();     // make it visible block-wide

        const ulonglong2* xs2 = (const ulonglong2*)(x_s + (c & 1) * XBUF_FL);
        const ulonglong2* ws2 = (const ulonglong2*)(w_s + (c & 1) * WBUF_FL);

#pragma unroll
        for (int u = 0; u < 4; u++) {
            const int kb = ks * 4 + u;
            ulonglong2 wv[4];
#pragma unroll
            for (int j = 0; j < 4; j++) wv[j] = ws2[(eg + 8 * j) * XS2 + kb];
#pragma unroll
            for (int i = 0; i < 8; i++) {
                ulonglong2 xv = xs2[(tg + 8 * i) * XS2 + kb];
#pragma unroll
                for (int j = 0; j < 4; j++) {
                    FMA2(acc[i][j], xv.x, wv[j].x);
                    FMA2(acc[i][j], xv.y, wv[j].y);
                }
            }
        }
        __syncthreads();     // protect buffer reuse by next prefetch
    }

    // reduce packed accumulators + 4 K-slices into hsum[token][expert] (aliased smem)
    for (int r = 0; r < 4; r++) {
        if (ks == r) {
#pragma unroll
            for (int i = 0; i < 8; i++)
#pragma unroll
                for (int j = 0; j < 4; j++) {
                    unsigned lo, hi;
                    asm("mov.b64 {%0,%1}, %2;" : "=r"(lo), "=r"(hi) : "l"(acc[i][j]));
                    float v = __uint_as_float(lo) + __uint_as_float(hi);
                    int t = tg + 8 * i, e = eg + 8 * j;
                    if (r == 0) hsum[t * HS + e] = v;
                    else        hsum[t * HS + e] += v;
                }
        }
        __syncthreads();
    }

    // ---- epilogue: one thread per token ----
    if (tid < TOK_PB) {
        const int t = tid;
        const int tok = tok0 + t;

        float g[NEXP], ctrl[NEXP], lg[NEXP], ln[NEXP], lo[NEXP];
#pragma unroll
        for (int e = 0; e < NEXP; e++) g[e] = tanhf(hsum[t * HS + e]);
#pragma unroll
        for (int e = 0; e < NEXP; e++) {
            float v = hsum[t * HS + NEXP + e];
            float sp = (v > 20.f) ? v : log1pf(__expf(v));
            ctrl[e] = sp + 0.01f;   // NOISE_EPS
        }
#pragma unroll
        for (int f = 0; f < NEXP; f++) {
            float s = 0.f;
#pragma unroll
            for (int e = 0; e < NEXP; e++) s = fmaf(g[e], w2_s[f * NEXP + e], s);
            lg[f] = s;
        }
#pragma unroll
        for (int f = 0; f < NEXP; f++) {
            ln[f] = noise[(size_t)tok * NEXP + f] * ctrl[f];
            lo[f] = lg[f] + ln[f];
        }

        // top-5 (stable: ties keep smaller index)
        float tv[5]; int tix[5]; unsigned used = 0;
#pragma unroll
        for (int p = 0; p < 5; p++) {
            float best = -1e30f; int bi = 0;
#pragma unroll
            for (int f = 0; f < NEXP; f++) {
                bool ok = !((used >> f) & 1u) && (lo[f] > best);
                best = ok ? lo[f] : best;
                bi   = ok ? f     : bi;
            }
            used |= 1u << bi;
            tv[p] = best; tix[p] = bi;
        }

        // softmax over top-4
        float ex[NSEL], ssum = 0.f;
#pragma unroll
        for (int p = 0; p < NSEL; p++) { ex[p] = __expf(tv[p] - tv[0]); ssum += ex[p]; }
        float inv = 1.f / ssum;
#pragma unroll
        for (int p = 0; p < NSEL; p++) {
            float sc = ex[p] * inv;
            out[(size_t)tok * NSEL + p] = (float)tix[p];                    // indices
            out[(size_t)N_TOKEN * NSEL + (size_t)tok * NSEL + p] = sc;      // scores
            atomicAdd(&imp_s[tix[p]], sc);
        }

        const float thr_in  = tv[4];
        const float thr_out = tv[3];
#pragma unroll
        for (int f = 0; f < NEXP; f++) {
            float thr = (ln[f] > thr_in) ? thr_in : thr_out;
            float z = (lg[f] - thr) / ctrl[f];
            atomicAdd(&load_s[f], normcdff(z));
        }
    }
    __syncthreads();
    if (tid < 32) {
        float v = (tid < NEXP) ? imp_s[tid] : load_s[tid - NEXP];
        g_part[blockIdx.x * 32 + tid] = v;
    }
}

__global__ __launch_bounds__(256)
void loss_kernel(float* __restrict__ out)
{
    __shared__ float red[32][8];
    const int e = threadIdx.x & 31;      // 0..31 (imp 0-15, load 16-31)
    const int c = threadIdx.x >> 5;      // 0..7 block-chunk
    float s = 0.f;
#pragma unroll
    for (int b = 0; b < NBLOCKS / 8; b++)
        s += g_part[(size_t)(c * (NBLOCKS / 8) + b) * 32 + e];
    red[e][c] = s;
    __syncthreads();
    if (threadIdx.x == 0) {
        double si = 0, sqi = 0, sl = 0, sql = 0;
        for (int k = 0; k < 32; k++) {
            double v = 0;
            for (int cc = 0; cc < 8; cc++) v += (double)red[k][cc];
            if (k < NEXP) { si += v; sqi += v * v; }
            else          { sl += v; sql += v * v; }
        }
        double mi = si / NEXP, ml = sl / NEXP;
        double vi = (sqi - si * si / NEXP) / (NEXP - 1);
        double vl = (sql - sl * sl / NEXP) / (NEXP - 1);
        double cv = vi / (mi * mi + 1e-10) + vl / (ml * ml + 1e-10);
        out[(size_t)2 * N_TOKEN * NSEL] = (float)(0.01 * cv);
    }
}

extern "C" void kernel_launch(void* const* d_in, const int* in_sizes, int n_in,
                              void* d_out, int out_size)
{
    const float* x     = (const float*)d_in[0];
    const float* w1    = (const float*)d_in[1];
    const float* w2    = (const float*)d_in[2];
    const float* wn    = (const float*)d_in[3];
    const float* noise = (const float*)d_in[4];
    float* out = (float*)d_out;

    cudaFuncSetAttribute(gate_kernel,
                         cudaFuncAttributeMaxDynamicSharedMemorySize, DSMEM_BYTES);
    gate_kernel<<<NBLOCKS, NTHREADS, DSMEM_BYTES>>>(x, w1, w2, wn, noise, out);
    loss_kernel<<<1, 256>>>(out);
}

// round 6
// speedup vs baseline: 1.1338x; 1.0151x over previous
#include <cuda_runtime.h>
#include <cuda_bf16.h>
#include <math.h>
#include <stdint.h>

#define N_TOKEN 16384
#define DMODEL  4096
#define NEXP    16
#define NSEL    4
#define M_TILE  128
#define NBLOCKS (N_TOKEN / M_TILE)   // 128
#define NTHREADS 256
#define KC      64                   // K elements per chunk
#define NCHUNK  (DMODEL / KC)        // 64
#define KSTEPS  (KC / 16)            // 4

#define XR 68                        // x smem row stride (floats)
#define WR 72                        // w smem row stride (bf16)
#define XBUF (M_TILE * XR)
#define WPLANE (32 * WR)
#define WBUF (3 * WPLANE)            // hi+mid+lo planes
#define NSTAGE 3
#define DSMEM (NSTAGE * XBUF * 4 + NSTAGE * WBUF * 2)
#define HS 33

__device__ __nv_bfloat16 g_wh[32 * DMODEL];
__device__ __nv_bfloat16 g_wm[32 * DMODEL];
__device__ __nv_bfloat16 g_wl[32 * DMODEL];
__device__ float g_imp[NEXP];
__device__ float g_load[NEXP];
__device__ unsigned g_count;

#define CP_ASYNC16(dst_s, src_g) \
    asm volatile("cp.async.cg.shared.global [%0], [%1], 16;" :: "r"(dst_s), "l"(src_g))
#define CP_COMMIT() asm volatile("cp.async.commit_group;")
#define CP_WAIT2()  asm volatile("cp.async.wait_group 2;")

#define MMA_BF16(d, a, b) \
    asm volatile("mma.sync.aligned.m16n8k16.row.col.f32.bf16.bf16.f32 " \
        "{%0,%1,%2,%3},{%4,%5,%6,%7},{%8,%9},{%0,%1,%2,%3};" \
        : "+f"(d[0]), "+f"(d[1]), "+f"(d[2]), "+f"(d[3]) \
        : "r"(a[0]), "r"(a[1]), "r"(a[2]), "r"(a[3]), "r"(b[0]), "r"(b[1]))

// 3-way bf16 split of an fp32 pair: v = h + m + l (exact; fp32 has 24 = 3x8 bits)
__device__ __forceinline__ void split3(float2 v, uint32_t& h, uint32_t& m, uint32_t& l) {
    asm("cvt.rn.bf16x2.f32 %0, %1, %2;" : "=r"(h) : "f"(v.y), "f"(v.x));
    float rx = v.x - __uint_as_float(h << 16);
    float ry = v.y - __uint_as_float(h & 0xffff0000u);
    asm("cvt.rn.bf16x2.f32 %0, %1, %2;" : "=r"(m) : "f"(ry), "f"(rx));
    float sx = rx - __uint_as_float(m << 16);
    float sy = ry - __uint_as_float(m & 0xffff0000u);
    asm("cvt.rn.bf16x2.f32 %0, %1, %2;" : "=r"(l) : "f"(sy), "f"(sx));
}

__global__ void wsplit_kernel(const float* __restrict__ w1,
                              const float* __restrict__ wn)
{
    int i = blockIdx.x * blockDim.x + threadIdx.x;   // 0 .. 131071
    int e = i >> 12, k = i & (DMODEL - 1);
    float v = (e < NEXP) ? w1[e * DMODEL + k] : wn[(e - NEXP) * DMODEL + k];
    __nv_bfloat16 h = __float2bfloat16(v);
    float r = v - __bfloat162float(h);
    __nv_bfloat16 m = __float2bfloat16(r);
    __nv_bfloat16 l = __float2bfloat16(r - __bfloat162float(m));
    g_wh[i] = h; g_wm[i] = m; g_wl[i] = l;
}

__global__ __launch_bounds__(NTHREADS)
void gate_kernel(const float* __restrict__ x,
                 const float* __restrict__ w2,
                 const float* __restrict__ noise,
                 float* __restrict__ out)
{
    extern __shared__ __align__(16) char dyn[];
    float* x_s = (float*)dyn;
    __nv_bfloat16* w_s = (__nv_bfloat16*)(dyn + NSTAGE * XBUF * 4);

    __shared__ float w2_s[NEXP * NEXP];
    __shared__ float imp_s[NEXP];
    __shared__ float load_s[NEXP];
    __shared__ int s_last;

    const int tid  = threadIdx.x;
    const int warp = tid >> 5;
    const int lane = tid & 31;
    const int group = lane >> 2;
    const int tg = lane & 3;
    const int tok0 = blockIdx.x * M_TILE;

    w2_s[tid] = w2[tid];
    if (tid < NEXP) { imp_s[tid] = 0.f; load_s[tid] = 0.f; }

    const int xrow_lo = tid >> 4;
    const int xq = tid & 15;
    const int wrow = (tid >> 3) & 31;
    const int wq = tid & 7;

    auto prefetch = [&](int c) {
        const int st = c % NSTAGE;
        float* xb = x_s + st * XBUF;
        __nv_bfloat16* wb = w_s + st * WBUF;
        const float* xsrc = x + (size_t)tok0 * DMODEL + c * KC;
#pragma unroll
        for (int r = 0; r < 8; r++) {
            int row = r * 16 + xrow_lo;
            uint32_t dst = (uint32_t)__cvta_generic_to_shared(xb + row * XR + xq * 4);
            CP_ASYNC16(dst, xsrc + (size_t)row * DMODEL + xq * 4);
        }
        const __nv_bfloat16* wsrc[3] = {g_wh, g_wm, g_wl};
#pragma unroll
        for (int plane = 0; plane < 3; plane++) {
            uint32_t dst = (uint32_t)__cvta_generic_to_shared(
                wb + plane * WPLANE + wrow * WR + wq * 8);
            CP_ASYNC16(dst, wsrc[plane] + (size_t)wrow * DMODEL + c * KC + wq * 8);
        }
        CP_COMMIT();
    };

    prefetch(0); prefetch(1); prefetch(2);

    // dH: hh chain (drained every 2 chunks into mst, IEEE fp32)
    // dM: 2^-8 terms; dL: 2^-16 terms (magnitudes too small to need drains)
    float dH[4][4], dM[4][4], dL[4][4], mst[4][4];
#pragma unroll
    for (int nt = 0; nt < 4; nt++)
#pragma unroll
        for (int q = 0; q < 4; q++) {
            dH[nt][q] = 0.f; dM[nt][q] = 0.f; dL[nt][q] = 0.f; mst[nt][q] = 0.f;
        }

    const int arow0 = warp * 16 + group;

    for (int c = 0; c < NCHUNK; c++) {
        const int st = c % NSTAGE;
        CP_WAIT2();
        __syncthreads();

        const float* xb = x_s + st * XBUF;
        const __nv_bfloat16* wh = w_s + st * WBUF;
        const __nv_bfloat16* wm = wh + WPLANE;
        const __nv_bfloat16* wl = wm + WPLANE;

#pragma unroll
        for (int s = 0; s < KSTEPS; s++) {
            const int k0 = s * 16;
            float2 va00 = *(const float2*)(xb + arow0 * XR + k0 + tg * 2);
            float2 va10 = *(const float2*)(xb + (arow0 + 8) * XR + k0 + tg * 2);
            float2 va01 = *(const float2*)(xb + arow0 * XR + k0 + tg * 2 + 8);
            float2 va11 = *(const float2*)(xb + (arow0 + 8) * XR + k0 + tg * 2 + 8);
            uint32_t ah[4], am[4], al[4];
            split3(va00, ah[0], am[0], al[0]);
            split3(va10, ah[1], am[1], al[1]);
            split3(va01, ah[2], am[2], al[2]);
            split3(va11, ah[3], am[3], al[3]);
#pragma unroll
            for (int nt = 0; nt < 4; nt++) {
                const int n = nt * 8 + group;
                uint32_t bh[2], bm[2], bl[2];
                bh[0] = *(const uint32_t*)(wh + n * WR + k0 + tg * 2);
                bh[1] = *(const uint32_t*)(wh + n * WR + k0 + tg * 2 + 8);
                bm[0] = *(const uint32_t*)(wm + n * WR + k0 + tg * 2);
                bm[1] = *(const uint32_t*)(wm + n * WR + k0 + tg * 2 + 8);
                bl[0] = *(const uint32_t*)(wl + n * WR + k0 + tg * 2);
                bl[1] = *(const uint32_t*)(wl + n * WR + k0 + tg * 2 + 8);
                MMA_BF16(dH[nt], ah, bh);   // h*h  (2^0)
                MMA_BF16(dM[nt], am, bh);   // m*h  (2^-8)
                MMA_BF16(dM[nt], ah, bm);   // h*m  (2^-8)
                MMA_BF16(dL[nt], al, bh);   // l*h  (2^-16)
                MMA_BF16(dL[nt], am, bm);   // m*m  (2^-16)
                MMA_BF16(dL[nt], ah, bl);   // h*l  (2^-16)
            }
        }

        // drain hh chain into IEEE fp32 master every 2 chunks
        if ((c & 1) == 1) {
#pragma unroll
            for (int nt = 0; nt < 4; nt++)
#pragma unroll
                for (int q = 0; q < 4; q++) {
                    mst[nt][q] += dH[nt][q];
                    dH[nt][q] = 0.f;
                }
        }

        __syncthreads();
        if (c + 3 < NCHUNK) prefetch(c + 3);
        else CP_COMMIT();
    }

    // ---- D -> hsum (alias stage-0 x buffer) ----
    float* hsum = x_s;
    __syncthreads();
#pragma unroll
    for (int nt = 0; nt < 4; nt++) {
        int col = nt * 8 + tg * 2;
#pragma unroll
        for (int q = 0; q < 4; q++) {
            float v = mst[nt][q] + dH[nt][q] + (dM[nt][q] + dL[nt][q]);
            int row = (q < 2) ? arow0 : arow0 + 8;
            hsum[row * HS + col + (q & 1)] = v;
        }
    }
    __syncthreads();

    // ---- epilogue: one thread per token ----
    if (tid < M_TILE) {
        const int t = tid;
        const int tok = tok0 + t;
        float g[NEXP], ctrl[NEXP], lg[NEXP], ln[NEXP], lo[NEXP];
#pragma unroll
        for (int e = 0; e < NEXP; e++) g[e] = tanhf(hsum[t * HS + e]);
#pragma unroll
        for (int e = 0; e < NEXP; e++) {
            float v = hsum[t * HS + NEXP + e];
            float sp = (v > 20.f) ? v : log1pf(__expf(v));
            ctrl[e] = sp + 0.01f;   // NOISE_EPS
        }
#pragma unroll
        for (int f = 0; f < NEXP; f++) {
            float s = 0.f;
#pragma unroll
            for (int e = 0; e < NEXP; e++) s = fmaf(g[e], w2_s[f * NEXP + e], s);
            lg[f] = s;
        }
        const float4* np = (const float4*)(noise + (size_t)tok * NEXP);
        float4 nz0 = np[0], nz1 = np[1], nz2 = np[2], nz3 = np[3];
        float nf[NEXP] = {nz0.x, nz0.y, nz0.z, nz0.w, nz1.x, nz1.y, nz1.z, nz1.w,
                          nz2.x, nz2.y, nz2.z, nz2.w, nz3.x, nz3.y, nz3.z, nz3.w};
#pragma unroll
        for (int f = 0; f < NEXP; f++) {
            ln[f] = nf[f] * ctrl[f];
            lo[f] = lg[f] + ln[f];
        }

        // top-5 (stable: ties keep smaller index)
        float tv[5]; int tix[5]; unsigned used = 0;
#pragma unroll
        for (int p = 0; p < 5; p++) {
            float best = -1e30f; int bi = 0;
#pragma unroll
            for (int f = 0; f < NEXP; f++) {
                bool ok = !((used >> f) & 1u) && (lo[f] > best);
                best = ok ? lo[f] : best;
                bi   = ok ? f     : bi;
            }
            used |= 1u << bi;
            tv[p] = best; tix[p] = bi;
        }

        float ex[NSEL], ssum = 0.f;
#pragma unroll
        for (int p = 0; p < NSEL; p++) { ex[p] = __expf(tv[p] - tv[0]); ssum += ex[p]; }
        float inv = 1.f / ssum;
#pragma unroll
        for (int p = 0; p < NSEL; p++) {
            float sc = ex[p] * inv;
            out[(size_t)tok * NSEL + p] = (float)tix[p];
            out[(size_t)N_TOKEN * NSEL + (size_t)tok * NSEL + p] = sc;
            atomicAdd(&imp_s[tix[p]], sc);
        }
        const float thr_in  = tv[4];
        const float thr_out = tv[3];
#pragma unroll
        for (int f = 0; f < NEXP; f++) {
            float thr = (ln[f] > thr_in) ? thr_in : thr_out;
            atomicAdd(&load_s[f], normcdff((lg[f] - thr) / ctrl[f]));
        }
    }
    __syncthreads();

    // ---- fused loss: global atomics, last block reduces ----
    if (tid < NEXP) {
        atomicAdd(&g_imp[tid],  imp_s[tid]);
        atomicAdd(&g_load[tid], load_s[tid]);
        __threadfence();
    }
    __syncthreads();
    if (tid == 0) s_last = (atomicAdd(&g_count, 1u) == NBLOCKS - 1);
    __syncthreads();
    if (s_last && tid == 0) {
        volatile float* vi = g_imp;
        volatile float* vl = g_load;
        double si = 0, sqi = 0, sl = 0, sql = 0;
        for (int e = 0; e < NEXP; e++) {
            double a = (double)vi[e]; si += a; sqi += a * a;
            double b = (double)vl[e]; sl += b; sql += b * b;
        }
        double mi = si / NEXP, ml = sl / NEXP;
        double viv = (sqi - si * si / NEXP) / (NEXP - 1);
        double vlv = (sql - sl * sl / NEXP) / (NEXP - 1);
        double cv = viv / (mi * mi + 1e-10) + vlv / (ml * ml + 1e-10);
        out[(size_t)2 * N_TOKEN * NSEL] = (float)(0.01 * cv);
        for (int e = 0; e < NEXP; e++) { g_imp[e] = 0.f; g_load[e] = 0.f; }
        g_count = 0;
    }
}

extern "C" void kernel_launch(void* const* d_in, const int* in_sizes, int n_in,
                              void* d_out, int out_size)
{
    const float* x     = (const float*)d_in[0];
    const float* w1    = (const float*)d_in[1];
    const float* w2    = (const float*)d_in[2];
    const float* wn    = (const float*)d_in[3];
    const float* noise = (const float*)d_in[4];
    float* out = (float*)d_out;

    wsplit_kernel<<<(32 * DMODEL) / NTHREADS, NTHREADS>>>(w1, wn);
    cudaFuncSetAttribute(gate_kernel,
                         cudaFuncAttributeMaxDynamicSharedMemorySize, DSMEM);
    gate_kernel<<<NBLOCKS, NTHREADS, DSMEM>>>(x, w2, noise, out);
}

// round 7
// speedup vs baseline: 1.3560x; 1.1960x over previous
#include <cuda_runtime.h>
#include <cuda_bf16.h>
#include <math.h>
#include <stdint.h>

#define N_TOKEN 16384
#define DMODEL  4096
#define NEXP    16
#define NSEL    4
#define M_TILE  64
#define NBLOCKS (N_TOKEN / M_TILE)   // 256
#define NTHREADS 256
#define KC      64                   // K elements per chunk
#define NCHUNK  (DMODEL / KC)        // 64
#define KSTEPS  (KC / 16)            // 4

#define XR 68                        // x smem row stride (floats)
#define WR 72                        // w smem row stride (bf16)
#define XBUF (M_TILE * XR)
#define WPLANE (32 * WR)
#define WBUF (3 * WPLANE)            // hi+mid+lo planes
#define NSTAGE 3
#define DSMEM (NSTAGE * XBUF * 4 + NSTAGE * WBUF * 2)   // ~94 KB
#define HS 33

__device__ __nv_bfloat16 g_wh[32 * DMODEL];
__device__ __nv_bfloat16 g_wm[32 * DMODEL];
__device__ __nv_bfloat16 g_wl[32 * DMODEL];
__device__ float g_imp[NEXP];
__device__ float g_load[NEXP];
__device__ unsigned g_count;

#define CP_ASYNC16(dst_s, src_g) \
    asm volatile("cp.async.cg.shared.global [%0], [%1], 16;" :: "r"(dst_s), "l"(src_g))
#define CP_COMMIT() asm volatile("cp.async.commit_group;")
#define CP_WAIT2()  asm volatile("cp.async.wait_group 2;")

#define MMA_BF16(d, a, b) \
    asm volatile("mma.sync.aligned.m16n8k16.row.col.f32.bf16.bf16.f32 " \
        "{%0,%1,%2,%3},{%4,%5,%6,%7},{%8,%9},{%0,%1,%2,%3};" \
        : "+f"(d[0]), "+f"(d[1]), "+f"(d[2]), "+f"(d[3]) \
        : "r"(a[0]), "r"(a[1]), "r"(a[2]), "r"(a[3]), "r"(b[0]), "r"(b[1]))

// 3-way bf16 split of an fp32 pair: v = h + m + l (exact; fp32 has 24 = 3x8 bits)
__device__ __forceinline__ void split3(float2 v, uint32_t& h, uint32_t& m, uint32_t& l) {
    asm("cvt.rn.bf16x2.f32 %0, %1, %2;" : "=r"(h) : "f"(v.y), "f"(v.x));
    float rx = v.x - __uint_as_float(h << 16);
    float ry = v.y - __uint_as_float(h & 0xffff0000u);
    asm("cvt.rn.bf16x2.f32 %0, %1, %2;" : "=r"(m) : "f"(ry), "f"(rx));
    float sx = rx - __uint_as_float(m << 16);
    float sy = ry - __uint_as_float(m & 0xffff0000u);
    asm("cvt.rn.bf16x2.f32 %0, %1, %2;" : "=r"(l) : "f"(sy), "f"(sx));
}

__global__ void wsplit_kernel(const float* __restrict__ w1,
                              const float* __restrict__ wn)
{
    int i = blockIdx.x * blockDim.x + threadIdx.x;   // 0 .. 131071
    int e = i >> 12, k = i & (DMODEL - 1);
    float v = (e < NEXP) ? w1[e * DMODEL + k] : wn[(e - NEXP) * DMODEL + k];
    __nv_bfloat16 h = __float2bfloat16(v);
    float r = v - __bfloat162float(h);
    __nv_bfloat16 m = __float2bfloat16(r);
    __nv_bfloat16 l = __float2bfloat16(r - __bfloat162float(m));
    g_wh[i] = h; g_wm[i] = m; g_wl[i] = l;
}

__global__ __launch_bounds__(NTHREADS)
void gate_kernel(const float* __restrict__ x,
                 const float* __restrict__ w2,
                 const float* __restrict__ noise,
                 float* __restrict__ out)
{
    extern __shared__ __align__(16) char dyn[];
    float* x_s = (float*)dyn;
    __nv_bfloat16* w_s = (__nv_bfloat16*)(dyn + NSTAGE * XBUF * 4);

    __shared__ float w2_s[NEXP * NEXP];
    __shared__ float imp_s[NEXP];
    __shared__ float load_s[NEXP];
    __shared__ int s_last;

    const int tid  = threadIdx.x;
    const int warp = tid >> 5;
    const int lane = tid & 31;
    const int group = lane >> 2;
    const int tg = lane & 3;
    const int tok0 = blockIdx.x * M_TILE;

    // warp -> (m-tile, n-half)
    const int mrow  = warp & 3;          // m16 tile 0..3
    const int nhalf = warp >> 2;         // 0: experts 0-15, 1: experts 16-31
    const int arow0 = mrow * 16 + group;

    w2_s[tid] = w2[tid];
    if (tid < NEXP) { imp_s[tid] = 0.f; load_s[tid] = 0.f; }

    const int xrow_lo = tid >> 4;        // 0..15
    const int xq = tid & 15;
    const int wrow = (tid >> 3) & 31;
    const int wq = tid & 7;

    auto prefetch = [&](int c) {
        const int st = c % NSTAGE;
        float* xb = x_s + st * XBUF;
        __nv_bfloat16* wb = w_s + st * WBUF;
        const float* xsrc = x + (size_t)tok0 * DMODEL + c * KC;
#pragma unroll
        for (int r = 0; r < 4; r++) {
            int row = r * 16 + xrow_lo;
            uint32_t dst = (uint32_t)__cvta_generic_to_shared(xb + row * XR + xq * 4);
            CP_ASYNC16(dst, xsrc + (size_t)row * DMODEL + xq * 4);
        }
        const __nv_bfloat16* wsrc[3] = {g_wh, g_wm, g_wl};
#pragma unroll
        for (int plane = 0; plane < 3; plane++) {
            uint32_t dst = (uint32_t)__cvta_generic_to_shared(
                wb + plane * WPLANE + wrow * WR + wq * 8);
            CP_ASYNC16(dst, wsrc[plane] + (size_t)wrow * DMODEL + c * KC + wq * 8);
        }
        CP_COMMIT();
    };

    prefetch(0); prefetch(1); prefetch(2);

    // dH: hh (drained every 2 chunks into IEEE fp32 mst); dM: 2^-8; dL: 2^-16
    float dH[2][4], dM[2][4], dL[2][4], mst[2][4];
#pragma unroll
    for (int nt = 0; nt < 2; nt++)
#pragma unroll
        for (int q = 0; q < 4; q++) {
            dH[nt][q] = 0.f; dM[nt][q] = 0.f; dL[nt][q] = 0.f; mst[nt][q] = 0.f;
        }

    for (int c = 0; c < NCHUNK; c++) {
        const int st = c % NSTAGE;
        CP_WAIT2();
        __syncthreads();

        const float* xb = x_s + st * XBUF;
        const __nv_bfloat16* wh = w_s + st * WBUF;
        const __nv_bfloat16* wm = wh + WPLANE;
        const __nv_bfloat16* wl = wm + WPLANE;

#pragma unroll
        for (int s = 0; s < KSTEPS; s++) {
            const int k0 = s * 16;
            float2 va00 = *(const float2*)(xb + arow0 * XR + k0 + tg * 2);
            float2 va10 = *(const float2*)(xb + (arow0 + 8) * XR + k0 + tg * 2);
            float2 va01 = *(const float2*)(xb + arow0 * XR + k0 + tg * 2 + 8);
            float2 va11 = *(const float2*)(xb + (arow0 + 8) * XR + k0 + tg * 2 + 8);
            uint32_t ah[4], am[4], al[4];
            split3(va00, ah[0], am[0], al[0]);
            split3(va10, ah[1], am[1], al[1]);
            split3(va01, ah[2], am[2], al[2]);
            split3(va11, ah[3], am[3], al[3]);
#pragma unroll
            for (int nt = 0; nt < 2; nt++) {
                const int n = nhalf * 16 + nt * 8 + group;
                uint32_t bh[2], bm[2], bl[2];
                bh[0] = *(const uint32_t*)(wh + n * WR + k0 + tg * 2);
                bh[1] = *(const uint32_t*)(wh + n * WR + k0 + tg * 2 + 8);
                bm[0] = *(const uint32_t*)(wm + n * WR + k0 + tg * 2);
                bm[1] = *(const uint32_t*)(wm + n * WR + k0 + tg * 2 + 8);
                bl[0] = *(const uint32_t*)(wl + n * WR + k0 + tg * 2);
                bl[1] = *(const uint32_t*)(wl + n * WR + k0 + tg * 2 + 8);
                MMA_BF16(dH[nt], ah, bh);   // h*h  (2^0)
                MMA_BF16(dM[nt], am, bh);   // m*h  (2^-8)
                MMA_BF16(dM[nt], ah, bm);   // h*m  (2^-8)
                MMA_BF16(dL[nt], al, bh);   // l*h  (2^-16)
                MMA_BF16(dL[nt], am, bm);   // m*m  (2^-16)
                MMA_BF16(dL[nt], ah, bl);   // h*l  (2^-16)
            }
        }

        // drain hh chain into IEEE fp32 master every 2 chunks
        if ((c & 1) == 1) {
#pragma unroll
            for (int nt = 0; nt < 2; nt++)
#pragma unroll
                for (int q = 0; q < 4; q++) {
                    mst[nt][q] += dH[nt][q];
                    dH[nt][q] = 0.f;
                }
        }

        __syncthreads();
        if (c + 3 < NCHUNK) prefetch(c + 3);
        else CP_COMMIT();
    }

    // ---- D -> hsum (alias stage-0 x buffer) ----
    float* hsum = x_s;
    __syncthreads();
#pragma unroll
    for (int nt = 0; nt < 2; nt++) {
        int col = nhalf * 16 + nt * 8 + tg * 2;
#pragma unroll
        for (int q = 0; q < 4; q++) {
            float v = mst[nt][q] + dH[nt][q] + (dM[nt][q] + dL[nt][q]);
            int row = (q < 2) ? arow0 : arow0 + 8;
            hsum[row * HS + col + (q & 1)] = v;
        }
    }
    __syncthreads();

    // ---- epilogue: one thread per token ----
    if (tid < M_TILE) {
        const int t = tid;
        const int tok = tok0 + t;
        float g[NEXP], ctrl[NEXP], lg[NEXP], ln[NEXP], lo[NEXP];
#pragma unroll
        for (int e = 0; e < NEXP; e++) g[e] = tanhf(hsum[t * HS + e]);
#pragma unroll
        for (int e = 0; e < NEXP; e++) {
            float v = hsum[t * HS + NEXP + e];
            float sp = (v > 20.f) ? v : log1pf(__expf(v));
            ctrl[e] = sp + 0.01f;   // NOISE_EPS
        }
#pragma unroll
        for (int f = 0; f < NEXP; f++) {
            float s = 0.f;
#pragma unroll
            for (int e = 0; e < NEXP; e++) s = fmaf(g[e], w2_s[f * NEXP + e], s);
            lg[f] = s;
        }
        const float4* np = (const float4*)(noise + (size_t)tok * NEXP);
        float4 nz0 = np[0], nz1 = np[1], nz2 = np[2], nz3 = np[3];
        float nf[NEXP] = {nz0.x, nz0.y, nz0.z, nz0.w, nz1.x, nz1.y, nz1.z, nz1.w,
                          nz2.x, nz2.y, nz2.z, nz2.w, nz3.x, nz3.y, nz3.z, nz3.w};
#pragma unroll
        for (int f = 0; f < NEXP; f++) {
            ln[f] = nf[f] * ctrl[f];
            lo[f] = lg[f] + ln[f];
        }

        // top-5 (stable: ties keep smaller index)
        float tv[5]; int tix[5]; unsigned used = 0;
#pragma unroll
        for (int p = 0; p < 5; p++) {
            float best = -1e30f; int bi = 0;
#pragma unroll
            for (int f = 0; f < NEXP; f++) {
                bool ok = !((used >> f) & 1u) && (lo[f] > best);
                best = ok ? lo[f] : best;
                bi   = ok ? f     : bi;
            }
            used |= 1u << bi;
            tv[p] = best; tix[p] = bi;
        }

        float ex[NSEL], ssum = 0.f;
#pragma unroll
        for (int p = 0; p < NSEL; p++) { ex[p] = __expf(tv[p] - tv[0]); ssum += ex[p]; }
        float inv = 1.f / ssum;
#pragma unroll
        for (int p = 0; p < NSEL; p++) {
            float sc = ex[p] * inv;
            out[(size_t)tok * NSEL + p] = (float)tix[p];
            out[(size_t)N_TOKEN * NSEL + (size_t)tok * NSEL + p] = sc;
            atomicAdd(&imp_s[tix[p]], sc);
        }
        const float thr_in  = tv[4];
        const float thr_out = tv[3];
#pragma unroll
        for (int f = 0; f < NEXP; f++) {
            float thr = (ln[f] > thr_in) ? thr_in : thr_out;
            atomicAdd(&load_s[f], normcdff((lg[f] - thr) / ctrl[f]));
        }
    }
    __syncthreads();

    // ---- fused loss: global atomics, last block reduces ----
    if (tid < NEXP) {
        atomicAdd(&g_imp[tid],  imp_s[tid]);
        atomicAdd(&g_load[tid], load_s[tid]);
        __threadfence();
    }
    __syncthreads();
    if (tid == 0) s_last = (atomicAdd(&g_count, 1u) == NBLOCKS - 1);
    __syncthreads();
    if (s_last && tid == 0) {
        volatile float* vi = g_imp;
        volatile float* vl = g_load;
        double si = 0, sqi = 0, sl = 0, sql = 0;
        for (int e = 0; e < NEXP; e++) {
            double a = (double)vi[e]; si += a; sqi += a * a;
            double b = (double)vl[e]; sl += b; sql += b * b;
        }
        double mi = si / NEXP, ml = sl / NEXP;
        double viv = (sqi - si * si / NEXP) / (NEXP - 1);
        double vlv = (sql - sl * sl / NEXP) / (NEXP - 1);
        double cv = viv / (mi * mi + 1e-10) + vlv / (ml * ml + 1e-10);
        out[(size_t)2 * N_TOKEN * NSEL] = (float)(0.01 * cv);
        for (int e = 0; e < NEXP; e++) { g_imp[e] = 0.f; g_load[e] = 0.f; }
        g_count = 0;
    }
}

extern "C" void kernel_launch(void* const* d_in, const int* in_sizes, int n_in,
                              void* d_out, int out_size)
{
    const float* x     = (const float*)d_in[0];
    const float* w1    = (const float*)d_in[1];
    const float* w2    = (const float*)d_in[2];
    const float* wn    = (const float*)d_in[3];
    const float* noise = (const float*)d_in[4];
    float* out = (float*)d_out;

    wsplit_kernel<<<(32 * DMODEL) / NTHREADS, NTHREADS>>>(w1, wn);
    cudaFuncSetAttribute(gate_kernel,
                         cudaFuncAttributeMaxDynamicSharedMemorySize, DSMEM);
    gate_kernel<<<NBLOCKS, NTHREADS, DSMEM>>>(x, w2, noise, out);
}

// round 8
// speedup vs baseline: 1.7118x; 1.2624x over previous
#include <cuda_runtime.h>
#include <cuda_fp16.h>
#include <math.h>
#include <stdint.h>

#define N_TOKEN 16384
#define DMODEL  4096
#define NEXP    16
#define NSEL    4
#define M_TILE  64
#define NBLOCKS (N_TOKEN / M_TILE)   // 256
#define NTHREADS 256
#define KC      64                   // K elements per chunk
#define NCHUNK  (DMODEL / KC)        // 64
#define KSTEPS  (KC / 16)            // 4

#define XR 68                        // x smem row stride (floats)
#define WR 72                        // w smem row stride (halves)
#define XBUF (M_TILE * XR)           // floats per x stage
#define WPLANE (32 * WR)             // halves per w plane
#define WBUF (2 * WPLANE)            // hi+lo planes
#define NSTAGE 4
#define DSMEM (NSTAGE * XBUF * 4 + NSTAGE * WBUF * 2)   // 106496 B
#define HS 33

__device__ __half g_wh[32 * DMODEL];
__device__ __half g_wl[32 * DMODEL];
__device__ float g_imp[NEXP];
__device__ float g_load[NEXP];
__device__ unsigned g_count;

#define CP_ASYNC16(dst_s, src_g) \
    asm volatile("cp.async.cg.shared.global [%0], [%1], 16;" :: "r"(dst_s), "l"(src_g))
#define CP_COMMIT() asm volatile("cp.async.commit_group;")
#define CP_WAIT2()  asm volatile("cp.async.wait_group 2;")

#define MMA_F16(d, a, b) \
    asm volatile("mma.sync.aligned.m16n8k16.row.col.f32.f16.f16.f32 " \
        "{%0,%1,%2,%3},{%4,%5,%6,%7},{%8,%9},{%0,%1,%2,%3};" \
        : "+f"(d[0]), "+f"(d[1]), "+f"(d[2]), "+f"(d[3]) \
        : "r"(a[0]), "r"(a[1]), "r"(a[2]), "r"(a[3]), "r"(b[0]), "r"(b[1]))

// 2-way fp16 split of an fp32 pair: v ~= h + l (to ~2^-23 relative)
__device__ __forceinline__ void split2h(float2 v, uint32_t& h, uint32_t& l) {
    __half2 hv = __float22half2_rn(v);          // lo = v.x, hi = v.y
    float2 hf = __half22float2(hv);
    __half2 lv = __float22half2_rn(make_float2(v.x - hf.x, v.y - hf.y));
    h = *reinterpret_cast<uint32_t*>(&hv);
    l = *reinterpret_cast<uint32_t*>(&lv);
}

// one-shot: split w1||wn into fp16 hi/lo planes
__global__ void wsplit_kernel(const float* __restrict__ w1,
                              const float* __restrict__ wn)
{
    int i = blockIdx.x * blockDim.x + threadIdx.x;   // 0 .. 131071
    int e = i >> 12, k = i & (DMODEL - 1);
    float v = (e < NEXP) ? w1[e * DMODEL + k] : wn[(e - NEXP) * DMODEL + k];
    __half h = __float2half_rn(v);
    g_wh[i] = h;
    g_wl[i] = __float2half_rn(v - __half2float(h));
}

__global__ __launch_bounds__(NTHREADS)
void gate_kernel(const float* __restrict__ x,
                 const float* __restrict__ w2,
                 const float* __restrict__ noise,
                 float* __restrict__ out)
{
    extern __shared__ __align__(16) char dyn[];
    float* x_s = (float*)dyn;
    __half* w_s = (__half*)(dyn + NSTAGE * XBUF * 4);

    __shared__ float w2_s[NEXP * NEXP];
    __shared__ float imp_s[NEXP];
    __shared__ float load_s[NEXP];
    __shared__ int s_last;

    const int tid  = threadIdx.x;
    const int warp = tid >> 5;
    const int lane = tid & 31;
    const int group = lane >> 2;
    const int tg = lane & 3;
    const int tok0 = blockIdx.x * M_TILE;

    // warp -> (m-tile, n-half)
    const int mrow  = warp & 3;          // m16 tile 0..3
    const int nhalf = warp >> 2;         // 0: experts 0-15, 1: experts 16-31
    const int arow0 = mrow * 16 + group;

    w2_s[tid] = w2[tid];
    if (tid < NEXP) { imp_s[tid] = 0.f; load_s[tid] = 0.f; }

    const int xrow_lo = tid >> 4;        // 0..15
    const int xq = tid & 15;
    const int wrow = (tid >> 3) & 31;
    const int wq = tid & 7;

    auto prefetch = [&](int c) {
        const int st = c % NSTAGE;
        float* xb = x_s + st * XBUF;
        __half* wb = w_s + st * WBUF;
        const float* xsrc = x + (size_t)tok0 * DMODEL + c * KC;
#pragma unroll
        for (int r = 0; r < 4; r++) {
            int row = r * 16 + xrow_lo;
            uint32_t dst = (uint32_t)__cvta_generic_to_shared(xb + row * XR + xq * 4);
            CP_ASYNC16(dst, xsrc + (size_t)row * DMODEL + xq * 4);
        }
        const __half* wsrc[2] = {g_wh, g_wl};
#pragma unroll
        for (int plane = 0; plane < 2; plane++) {
            uint32_t dst = (uint32_t)__cvta_generic_to_shared(
                wb + plane * WPLANE + wrow * WR + wq * 8);
            CP_ASYNC16(dst, wsrc[plane] + (size_t)wrow * DMODEL + c * KC + wq * 8);
        }
        CP_COMMIT();
    };

    prefetch(0); prefetch(1); prefetch(2);

    // dH: hh (drained every 2 chunks into IEEE fp32 mst); dM: xl*wh; dL: xh*wl
    float dH[2][4], dM[2][4], dL[2][4], mst[2][4];
#pragma unroll
    for (int nt = 0; nt < 2; nt++)
#pragma unroll
        for (int q = 0; q < 4; q++) {
            dH[nt][q] = 0.f; dM[nt][q] = 0.f; dL[nt][q] = 0.f; mst[nt][q] = 0.f;
        }

    for (int c = 0; c < NCHUNK; c++) {
        const int st = c % NSTAGE;
        CP_WAIT2();            // pending {c, c+1, c+2} -> group c complete
        __syncthreads();       // stage c visible block-wide

        // prefetch stage (c+3)%4 != c%4 — consumed at chunk c-1, all warps
        // are past their chunk-c top barrier, so reuse is safe without a
        // second sync. Empty commit keeps wait_group counts exact at tail.
        if (c + 3 < NCHUNK) prefetch(c + 3);
        else CP_COMMIT();

        const float* xb = x_s + st * XBUF;
        const __half* wh = w_s + st * WBUF;
        const __half* wl = wh + WPLANE;

#pragma unroll
        for (int s = 0; s < KSTEPS; s++) {
            const int k0 = s * 16;
            float2 va00 = *(const float2*)(xb + arow0 * XR + k0 + tg * 2);
            float2 va10 = *(const float2*)(xb + (arow0 + 8) * XR + k0 + tg * 2);
            float2 va01 = *(const float2*)(xb + arow0 * XR + k0 + tg * 2 + 8);
            float2 va11 = *(const float2*)(xb + (arow0 + 8) * XR + k0 + tg * 2 + 8);
            uint32_t ah[4], al[4];
            split2h(va00, ah[0], al[0]);
            split2h(va10, ah[1], al[1]);
            split2h(va01, ah[2], al[2]);
            split2h(va11, ah[3], al[3]);
#pragma unroll
            for (int nt = 0; nt < 2; nt++) {
                const int n = nhalf * 16 + nt * 8 + group;
                uint32_t bh[2], bl[2];
                bh[0] = *(const uint32_t*)(wh + n * WR + k0 + tg * 2);
                bh[1] = *(const uint32_t*)(wh + n * WR + k0 + tg * 2 + 8);
                bl[0] = *(const uint32_t*)(wl + n * WR + k0 + tg * 2);
                bl[1] = *(const uint32_t*)(wl + n * WR + k0 + tg * 2 + 8);
                MMA_F16(dH[nt], ah, bh);   // h*h  (2^0)
                MMA_F16(dM[nt], al, bh);   // l*h  (2^-12)
                MMA_F16(dL[nt], ah, bl);   // h*l  (2^-12)
            }
        }

        // drain hh chain into IEEE fp32 master every 2 chunks
        if ((c & 1) == 1) {
#pragma unroll
            for (int nt = 0; nt < 2; nt++)
#pragma unroll
                for (int q = 0; q < 4; q++) {
                    mst[nt][q] += dH[nt][q];
                    dH[nt][q] = 0.f;
                }
        }
    }

    // ---- D -> hsum (alias stage-0 x buffer) ----
    float* hsum = x_s;
    __syncthreads();
#pragma unroll
    for (int nt = 0; nt < 2; nt++) {
        int col = nhalf * 16 + nt * 8 + tg * 2;
#pragma unroll
        for (int q = 0; q < 4; q++) {
            float v = mst[nt][q] + dH[nt][q] + (dM[nt][q] + dL[nt][q]);
            int row = (q < 2) ? arow0 : arow0 + 8;
            hsum[row * HS + col + (q & 1)] = v;
        }
    }
    __syncthreads();

    // ---- epilogue: one thread per token ----
    if (tid < M_TILE) {
        const int t = tid;
        const int tok = tok0 + t;
        float g[NEXP], ctrl[NEXP], lg[NEXP], ln[NEXP], lo[NEXP];
#pragma unroll
        for (int e = 0; e < NEXP; e++) g[e] = tanhf(hsum[t * HS + e]);
#pragma unroll
        for (int e = 0; e < NEXP; e++) {
            float v = hsum[t * HS + NEXP + e];
            float sp = (v > 20.f) ? v : log1pf(__expf(v));
            ctrl[e] = sp + 0.01f;   // NOISE_EPS
        }
#pragma unroll
        for (int f = 0; f < NEXP; f++) {
            float s = 0.f;
#pragma unroll
            for (int e = 0; e < NEXP; e++) s = fmaf(g[e], w2_s[f * NEXP + e], s);
            lg[f] = s;
        }
        const float4* np = (const float4*)(noise + (size_t)tok * NEXP);
        float4 nz0 = np[0], nz1 = np[1], nz2 = np[2], nz3 = np[3];
        float nf[NEXP] = {nz0.x, nz0.y, nz0.z, nz0.w, nz1.x, nz1.y, nz1.z, nz1.w,
                          nz2.x, nz2.y, nz2.z, nz2.w, nz3.x, nz3.y, nz3.z, nz3.w};
#pragma unroll
        for (int f = 0; f < NEXP; f++) {
            ln[f] = nf[f] * ctrl[f];
            lo[f] = lg[f] + ln[f];
        }

        // top-5 (stable: ties keep smaller index)
        float tv[5]; int tix[5]; unsigned used = 0;
#pragma unroll
        for (int p = 0; p < 5; p++) {
            float best = -1e30f; int bi = 0;
#pragma unroll
            for (int f = 0; f < NEXP; f++) {
                bool ok = !((used >> f) & 1u) && (lo[f] > best);
                best = ok ? lo[f] : best;
                bi   = ok ? f     : bi;
            }
            used |= 1u << bi;
            tv[p] = best; tix[p] = bi;
        }

        float ex[NSEL], ssum = 0.f;
#pragma unroll
        for (int p = 0; p < NSEL; p++) { ex[p] = __expf(tv[p] - tv[0]); ssum += ex[p]; }
        float inv = 1.f / ssum;
#pragma unroll
        for (int p = 0; p < NSEL; p++) {
            float sc = ex[p] * inv;
            out[(size_t)tok * NSEL + p] = (float)tix[p];
            out[(size_t)N_TOKEN * NSEL + (size_t)tok * NSEL + p] = sc;
            atomicAdd(&imp_s[tix[p]], sc);
        }
        const float thr_in  = tv[4];
        const float thr_out = tv[3];
#pragma unroll
        for (int f = 0; f < NEXP; f++) {
            float thr = (ln[f] > thr_in) ? thr_in : thr_out;
            atomicAdd(&load_s[f], normcdff((lg[f] - thr) / ctrl[f]));
        }
    }
    __syncthreads();

    // ---- fused loss: global atomics, last block reduces ----
    if (tid < NEXP) {
        atomicAdd(&g_imp[tid],  imp_s[tid]);
        atomicAdd(&g_load[tid], load_s[tid]);
        __threadfence();
    }
    __syncthreads();
    if (tid == 0) s_last = (atomicAdd(&g_count, 1u) == NBLOCKS - 1);
    __syncthreads();
    if (s_last && tid == 0) {
        volatile float* vi = g_imp;
        volatile float* vl = g_load;
        double si = 0, sqi = 0, sl = 0, sql = 0;
        for (int e = 0; e < NEXP; e++) {
            double a = (double)vi[e]; si += a; sqi += a * a;
            double b = (double)vl[e]; sl += b; sql += b * b;
        }
        double mi = si / NEXP, ml = sl / NEXP;
        double viv = (sqi - si * si / NEXP) / (NEXP - 1);
        double vlv = (sql - sl * sl / NEXP) / (NEXP - 1);
        double cv = viv / (mi * mi + 1e-10) + vlv / (ml * ml + 1e-10);
        out[(size_t)2 * N_TOKEN * NSEL] = (float)(0.01 * cv);
        for (int e = 0; e < NEXP; e++) { g_imp[e] = 0.f; g_load[e] = 0.f; }
        g_count = 0;
    }
}

extern "C" void kernel_launch(void* const* d_in, const int* in_sizes, int n_in,
                              void* d_out, int out_size)
{
    const float* x     = (const float*)d_in[0];
    const float* w1    = (const float*)d_in[1];
    const float* w2    = (const float*)d_in[2];
    const float* wn    = (const float*)d_in[3];
    const float* noise = (const float*)d_in[4];
    float* out = (float*)d_out;

    wsplit_kernel<<<(32 * DMODEL) / NTHREADS, NTHREADS>>>(w1, wn);
    cudaFuncSetAttribute(gate_kernel,
                         cudaFuncAttributeMaxDynamicSharedMemorySize, DSMEM);
    gate_kernel<<<NBLOCKS, NTHREADS, DSMEM>>>(x, w2, noise, out);
}